// round 15
// baseline (speedup 1.0000x reference)
#include <cuda_runtime.h>
#include <cuda_fp16.h>
#include <cstdint>
#include <math.h>

// ---------------------------------------------------------------------------
// IntraSentenceGNN on GB300 (sm_103 base ISA): mma.sync fp16 GEMMs.
// R15: R14 GEMM (128-thr CTA, 64x64 warp tile, occ-2) unchanged; fold GEMM
// now writes transposed fp16 WfT directly from its epilogue (smem-staged),
// eliminating the fp32 Wf buffer and the convT pass.
// ---------------------------------------------------------------------------

#define BATCH 32768
#define HDIM  1024

typedef __half fp16;

// ------------------------------ scratch -----------------------------------
__device__ __align__(256) float g_bf [6 * 1024];
__device__ __align__(256) fp16 g_gl1[BATCH * 3 * HDIM];
__device__ __align__(256) fp16 g_gr1[BATCH * 3 * HDIM];
__device__ __align__(256) fp16 g_gl2[BATCH * 3 * HDIM];
__device__ __align__(256) fp16 g_gr2[BATCH * 3 * HDIM];

__device__ __align__(256) fp16 g_WmH [3 * 1024 * 1024];
__device__ __align__(256) fp16 g_WT1H[2 * 1024 * 1024];
__device__ __align__(256) fp16 g_WT1L[2 * 1024 * 1024];
__device__ __align__(256) fp16 g_WT2 [2 * 1024 * 1024];   // [Wl2^T | Wr2^T]
__device__ __align__(256) fp16 g_WfT [6 * 1024 * 1024];   // c = 2m+side
__device__ __align__(256) fp16 g_feat[3 * BATCH * 1024];
__device__ __align__(256) fp16 g_x1  [BATCH * 3 * 1024];

// --------------------------- PTX helpers ----------------------------------
__device__ __forceinline__ uint32_t smem_u32(const void* p) {
    uint32_t a;
    asm("{ .reg .u64 t; cvta.to.shared.u64 t, %1; cvt.u32.u64 %0, t; }"
        : "=r"(a) : "l"(p));
    return a;
}
__device__ __forceinline__ void cp16(uint32_t sdst, const void* gsrc) {
    asm volatile("cp.async.cg.shared.global [%0], [%1], 16;" :: "r"(sdst), "l"(gsrc));
}
__device__ __forceinline__ void cp_commit() {
    asm volatile("cp.async.commit_group;" ::: "memory");
}
__device__ __forceinline__ void cp_wait1() {
    asm volatile("cp.async.wait_group 1;" ::: "memory");
}
__device__ __forceinline__ void cp_wait0() {
    asm volatile("cp.async.wait_group 0;" ::: "memory");
}

__device__ __forceinline__ uint32_t sw_addr(uint32_t base, int row, int colb) {
    uint32_t off = (uint32_t)(row * 128 + colb);
    return base + (off ^ ((off >> 3) & 0x70));
}

__device__ __forceinline__ void ldsm4(uint32_t addr, uint32_t* r) {
    asm volatile("ldmatrix.sync.aligned.m8n8.x4.shared.b16 {%0,%1,%2,%3}, [%4];"
        : "=r"(r[0]), "=r"(r[1]), "=r"(r[2]), "=r"(r[3]) : "r"(addr));
}

__device__ __forceinline__ void mma16816(float* c, const uint32_t* a, const uint32_t* b) {
    asm volatile(
        "mma.sync.aligned.m16n8k16.row.col.f32.f16.f16.f32 "
        "{%0,%1,%2,%3}, {%4,%5,%6,%7}, {%8,%9}, {%0,%1,%2,%3};"
        : "+f"(c[0]), "+f"(c[1]), "+f"(c[2]), "+f"(c[3])
        : "r"(a[0]), "r"(a[1]), "r"(a[2]), "r"(a[3]), "r"(b[0]), "r"(b[1]));
}

// load ROWS x 64 fp16 subtile (swizzled) via cp.async, NT threads
template<int ROWS, int NT>
__device__ __forceinline__ void load_sub(const fp16* src, int blk, int ld,
                                         uint32_t rb, int kofs, int tid) {
    #pragma unroll
    for (int i = 0; i < (ROWS * 8) / NT; i++) {
        const int c = tid + i * NT;
        const int row = c >> 3, kc = c & 7;
        const void* g = src + (size_t)(blk + row) * ld + kofs + kc * 8;
        uint32_t off = (uint32_t)(row * 128 + kc * 16);
        off ^= (off >> 3) & 0x70;
        cp16(rb + off, g);
    }
}

// ---------------------------------------------------------------------------
// 1-term fp16 GEMM (R14, unchanged): 128-thread CTA, warp 64x64 (2m x 2n),
// CTA 128x128, occ-2, BK=64, 3-stage cp.async, grid.z batching.
// ---------------------------------------------------------------------------
#define SMEM_1T (3 * 32768)

__global__ __launch_bounds__(128, 2) void gemm_1t(
    int M, int K,
    const fp16* __restrict__ A, int lda, size_t aZ,
    const fp16* __restrict__ B, int ldb, size_t bZ,
    fp16* __restrict__ Cl, fp16* __restrict__ Cr, int ldc, size_t cZ,
    const float* __restrict__ biasL, const float* __restrict__ biasR, int biasZ)
{
    const int z = blockIdx.z;
    A += (size_t)z * aZ;
    B += (size_t)z * bZ;
    Cl += (size_t)z * cZ;
    Cr += (size_t)z * cZ;
    if (biasL) { biasL += (size_t)z * biasZ; biasR += (size_t)z * biasZ; }

    extern __shared__ char smem[];
    const uint32_t sbase = smem_u32(smem);
    const int tid  = threadIdx.x;
    const int wid  = tid >> 5;
    const int lane = tid & 31;
    const int warp_m = wid & 1;
    const int warp_n = wid >> 1;

    const int mblk = blockIdx.y * 128;
    const int nblk = blockIdx.x * 128;
    const int side = nblk >> 10;
    fp16* C = side ? Cr : Cl;
    const float* bias = side ? biasR : biasL;
    const int colbase = nblk & 1023;
    const int KT = K >> 6;

    auto load_tile = [&](int kt, int s) {
        const uint32_t st = sbase + s * 32768;
        load_sub<128, 128>(A, mblk, lda, st,         kt * 64, tid);
        load_sub<128, 128>(B, nblk, ldb, st + 16384, kt * 64, tid);
        cp_commit();
    };

    float acc[4][8][4];
    #pragma unroll
    for (int mt = 0; mt < 4; mt++)
        #pragma unroll
        for (int nt = 0; nt < 8; nt++)
            #pragma unroll
            for (int q = 0; q < 4; q++) acc[mt][nt][q] = 0.0f;

    load_tile(0, 0);
    load_tile(1, 1);

    const int qa_r = ((lane >> 3) & 1) * 8 + (lane & 7);
    const int qa_c = (lane >> 4) * 16;
    const int qb_r = (lane >> 4) * 8 + (lane & 7);
    const int qb_c = ((lane >> 3) & 1) * 16;

    for (int kt = 0; kt < KT; kt++) {
        if (kt + 1 < KT) cp_wait1(); else cp_wait0();
        __syncthreads();

        const uint32_t st = sbase + (kt % 3) * 32768;
        const uint32_t sA = st, sB = st + 16384;

        #pragma unroll
        for (int ks = 0; ks < 4; ks++) {
            uint32_t afr[4][4];
            #pragma unroll
            for (int mt = 0; mt < 4; mt++)
                ldsm4(sw_addr(sA, warp_m * 64 + mt * 16 + qa_r, ks * 32 + qa_c), afr[mt]);
            uint32_t bfr[8][2];
            #pragma unroll
            for (int p = 0; p < 4; p++) {
                uint32_t r[4];
                ldsm4(sw_addr(sB, warp_n * 64 + p * 16 + qb_r, ks * 32 + qb_c), r);
                bfr[2*p][0] = r[0]; bfr[2*p][1] = r[1];
                bfr[2*p+1][0] = r[2]; bfr[2*p+1][1] = r[3];
            }
            #pragma unroll
            for (int mt = 0; mt < 4; mt++)
                #pragma unroll
                for (int nt = 0; nt < 8; nt++)
                    mma16816(acc[mt][nt], afr[mt], bfr[nt]);
        }
        if (kt + 2 < KT) load_tile(kt + 2, (kt + 2) % 3);
    }

    #pragma unroll
    for (int mt = 0; mt < 4; mt++) {
        const int row = mblk + warp_m * 64 + mt * 16 + (lane >> 2);
        #pragma unroll
        for (int nt = 0; nt < 8; nt++) {
            const int col = colbase + warp_n * 64 + nt * 8 + (lane & 3) * 2;
            float b0 = 0.0f, b1 = 0.0f;
            if (bias) { b0 = bias[col]; b1 = bias[col + 1]; }
            *reinterpret_cast<__half2*>(C + (size_t)row * ldc + col) =
                __floats2half2_rn(acc[mt][nt][0] + b0, acc[mt][nt][1] + b1);
            *reinterpret_cast<__half2*>(C + (size_t)(row + 8) * ldc + col) =
                __floats2half2_rn(acc[mt][nt][2] + b0, acc[mt][nt][3] + b1);
        }
    }
}

// ---------------------------------------------------------------------------
// 2-term fold GEMM with direct transposed fp16 output (R15):
// c = blockIdx.z = 2m+side; WfT[c] = (Wm[m] @ W{l|r}1)^T as fp16.
// Output tile staged in smem (fp16, 136-elem padded rows), then written
// transposed with coalesced half2 stores.
// ---------------------------------------------------------------------------
#define SMEM_FOLD (3 * 49152)

__global__ __launch_bounds__(256, 1) void gemm_fold(
    const fp16* __restrict__ WmH,
    const fp16* __restrict__ W1H, const fp16* __restrict__ W1L,
    fp16* __restrict__ WfT, float scale)
{
    const size_t M1 = 1024 * 1024;
    const int c = blockIdx.z;
    const int m = c >> 1, side = c & 1;
    const fp16* A  = WmH + (size_t)m * M1;
    const fp16* Bh = W1H + (size_t)side * M1;
    const fp16* Bl = W1L + (size_t)side * M1;
    fp16* Cout = WfT + (size_t)c * M1;

    extern __shared__ char smem[];
    const uint32_t sbase = smem_u32(smem);
    const int tid  = threadIdx.x;
    const int wid  = tid >> 5;
    const int lane = tid & 31;
    const int warp_m = wid & 3;
    const int warp_n = wid >> 2;

    const int mblk = blockIdx.y * 128;
    const int nblk = blockIdx.x * 128;
    const int KT = 16;

    auto load_tile = [&](int kt, int s) {
        const uint32_t st = sbase + s * 49152;
        load_sub<128, 256>(A,  mblk, 1024, st,         kt * 64, tid);
        load_sub<128, 256>(Bh, nblk, 1024, st + 16384, kt * 64, tid);
        load_sub<128, 256>(Bl, nblk, 1024, st + 32768, kt * 64, tid);
        cp_commit();
    };

    float acc[2][8][4];
    #pragma unroll
    for (int mt = 0; mt < 2; mt++)
        #pragma unroll
        for (int nt = 0; nt < 8; nt++)
            #pragma unroll
            for (int q = 0; q < 4; q++) acc[mt][nt][q] = 0.0f;

    load_tile(0, 0);
    load_tile(1, 1);

    const int qa_r = ((lane >> 3) & 1) * 8 + (lane & 7);
    const int qa_c = (lane >> 4) * 16;
    const int qb_r = (lane >> 4) * 8 + (lane & 7);
    const int qb_c = ((lane >> 3) & 1) * 16;

    for (int kt = 0; kt < KT; kt++) {
        if (kt + 1 < KT) cp_wait1(); else cp_wait0();
        __syncthreads();

        const uint32_t st = sbase + (kt % 3) * 49152;
        const uint32_t sA = st, sBh = st + 16384, sBl = st + 32768;

        #pragma unroll
        for (int ks = 0; ks < 4; ks++) {
            uint32_t afr[2][4];
            #pragma unroll
            for (int mt = 0; mt < 2; mt++)
                ldsm4(sw_addr(sA, warp_m * 32 + mt * 16 + qa_r, ks * 32 + qa_c), afr[mt]);
            uint32_t bfH[8][2], bfL[8][2];
            #pragma unroll
            for (int p = 0; p < 4; p++) {
                const int rr = warp_n * 64 + p * 16 + qb_r;
                const int cc = ks * 32 + qb_c;
                uint32_t r[4];
                ldsm4(sw_addr(sBh, rr, cc), r);
                bfH[2*p][0] = r[0]; bfH[2*p][1] = r[1];
                bfH[2*p+1][0] = r[2]; bfH[2*p+1][1] = r[3];
                ldsm4(sw_addr(sBl, rr, cc), r);
                bfL[2*p][0] = r[0]; bfL[2*p][1] = r[1];
                bfL[2*p+1][0] = r[2]; bfL[2*p+1][1] = r[3];
            }
            #pragma unroll
            for (int mt = 0; mt < 2; mt++)
                #pragma unroll
                for (int nt = 0; nt < 8; nt++) {
                    mma16816(acc[mt][nt], afr[mt], bfH[nt]);
                    mma16816(acc[mt][nt], afr[mt], bfL[nt]);
                }
        }
        if (kt + 2 < KT) load_tile(kt + 2, (kt + 2) % 3);
    }

    // ---- epilogue: stage fp16 tile in smem, write transposed ----
    __syncthreads();   // all stage reads done; smem reusable
    fp16* tile = reinterpret_cast<fp16*>(smem);   // [128][136] padded

    #pragma unroll
    for (int mt = 0; mt < 2; mt++) {
        const int row = warp_m * 32 + mt * 16 + (lane >> 2);
        #pragma unroll
        for (int nt = 0; nt < 8; nt++) {
            const int col = warp_n * 64 + nt * 8 + (lane & 3) * 2;
            *reinterpret_cast<__half2*>(tile + row * 136 + col) =
                __floats2half2_rn(acc[mt][nt][0] * scale, acc[mt][nt][1] * scale);
            *reinterpret_cast<__half2*>(tile + (row + 8) * 136 + col) =
                __floats2half2_rn(acc[mt][nt][2] * scale, acc[mt][nt][3] * scale);
        }
    }
    __syncthreads();

    // transposed write: WfT row = output col (nblk+tc), col = output row (mblk+tr)
    #pragma unroll
    for (int i = 0; i < 32; i++) {
        const int idx = tid + i * 256;         // 0..8191 half2-pairs
        const int tr = (idx & 63) * 2;         // source row pair
        const int tc = idx >> 6;               // source col
        __half2 v = __halves2half2(tile[tr * 136 + tc], tile[(tr + 1) * 136 + tc]);
        *reinterpret_cast<__half2*>(Cout + (size_t)(nblk + tc) * 1024 + mblk + tr) = v;
    }
}

// ---------------------------------------------------------------------------
// mega_prep (unchanged)
// ---------------------------------------------------------------------------
__device__ __forceinline__ void split1(float x, fp16& h, fp16& l) {
    h = __float2half(x);
    l = __float2half(x - __half2float(h));
}

#define PREP_BLOCKS 19480

__global__ __launch_bounds__(256) void mega_prep(
    const float* __restrict__ Wl1, const float* __restrict__ Wr1,
    const float* __restrict__ Wl2, const float* __restrict__ Wr2,
    const float* __restrict__ Wm0, const float* __restrict__ Wm1,
    const float* __restrict__ Wm2,
    const float* __restrict__ f0, const float* __restrict__ f1,
    const float* __restrict__ f2,
    const float* __restrict__ bt, const float* __restrict__ ba,
    const float* __restrict__ bv,
    fp16* __restrict__ WT1H, fp16* __restrict__ WT1L, fp16* __restrict__ WT2,
    fp16* __restrict__ WmH, fp16* __restrict__ feat16,
    float* __restrict__ bf, float sfold)
{
    const size_t M1 = 1024 * 1024;
    __shared__ float t[32][33];
    const int bid = blockIdx.x;
    const int tid = threadIdx.x;
    const int tx = tid & 31, ty = tid >> 5;

    if (bid < 2048) {
        const int z = bid >> 10, tl = bid & 1023;
        const float* in = z ? Wr1 : Wl1;
        fp16* hi = WT1H + (size_t)z * M1;
        fp16* lo = WT1L + (size_t)z * M1;
        const int x0 = (tl & 31) * 32, y0 = (tl >> 5) * 32;
        #pragma unroll
        for (int r = ty; r < 32; r += 8)
            t[r][tx] = in[(size_t)(y0 + r) * 1024 + x0 + tx];
        __syncthreads();
        #pragma unroll
        for (int r = ty; r < 32; r += 8) {
            float v = t[tx][r] * sfold;
            fp16 h, l;
            split1(v, h, l);
            hi[(size_t)(x0 + r) * 1024 + y0 + tx] = h;
            lo[(size_t)(x0 + r) * 1024 + y0 + tx] = l;
        }
    } else if (bid < 4096) {
        const int rel = bid - 2048;
        const int z = rel >> 10, tl = rel & 1023;
        const float* in = z ? Wr2 : Wl2;
        fp16* o = WT2 + (size_t)z * M1;
        const int x0 = (tl & 31) * 32, y0 = (tl >> 5) * 32;
        #pragma unroll
        for (int r = ty; r < 32; r += 8)
            t[r][tx] = in[(size_t)(y0 + r) * 1024 + x0 + tx];
        __syncthreads();
        #pragma unroll
        for (int r = ty; r < 32; r += 8)
            o[(size_t)(x0 + r) * 1024 + y0 + tx] = __float2half(t[tx][r]);
    } else if (bid < 7168) {
        const int rel = bid - 4096;
        const int m = rel >> 10, blk = rel & 1023;
        const float* in = (m == 0) ? Wm0 : (m == 1) ? Wm1 : Wm2;
        fp16* o = WmH + (size_t)m * M1;
        const int i = blk * 1024 + tid * 4;
        float4 v = *reinterpret_cast<const float4*>(in + i);
        *reinterpret_cast<__half2*>(o + i)     = __floats2half2_rn(v.x, v.y);
        *reinterpret_cast<__half2*>(o + i + 2) = __floats2half2_rn(v.z, v.w);
    } else if (bid < 19456) {
        const int rel = bid - 7168;
        const int m = rel / 4096, blk = rel % 4096;
        const float* in = (m == 0) ? f0 : (m == 1) ? f1 : f2;
        fp16* o = feat16 + (size_t)m * BATCH * 1024;
        const int base = blk * 8192;
        #pragma unroll
        for (int u = 0; u < 8; u++) {
            const int i = base + (u * 256 + tid) * 4;
            float4 v = *reinterpret_cast<const float4*>(in + i);
            *reinterpret_cast<__half2*>(o + i)     = __floats2half2_rn(v.x, v.y);
            *reinterpret_cast<__half2*>(o + i + 2) = __floats2half2_rn(v.z, v.w);
        }
    } else {
        const int g = (bid - 19456) * 256 + tid;
        const int combo = g >> 10, j = g & 1023;
        const int m = combo % 3;
        const float* bvec = (m == 0) ? bt : (m == 1) ? ba : bv;
        const float* W = (combo < 3) ? Wl1 : Wr1;
        float s = 0.0f;
        for (int k = 0; k < 1024; k++) s += bvec[k] * W[k * 1024 + j];
        bf[g] = s;
    }
}

// ---------------------------------------------------------------------------
// attention kernels (unchanged)
// ---------------------------------------------------------------------------
__device__ __forceinline__ float lrelu02(float x) { return x > 0.0f ? x : 0.2f * x; }

__device__ __forceinline__ float4 ld4h(const fp16* p) {
    uint2 u = *reinterpret_cast<const uint2*>(p);
    float2 f01 = __half22float2(*reinterpret_cast<__half2*>(&u.x));
    float2 f23 = __half22float2(*reinterpret_cast<__half2*>(&u.y));
    return make_float4(f01.x, f01.y, f23.x, f23.y);
}

__global__ __launch_bounds__(256) void gat1_kernel(
    const fp16* __restrict__ gl, const fp16* __restrict__ gr,
    const float* __restrict__ att, const float* __restrict__ b1,
    fp16* __restrict__ x1)
{
    const int b = blockIdx.x;
    const int h = threadIdx.x >> 5;
    const int lane = threadIdx.x & 31;
    const int dbase = lane * 4;

    const size_t base = (size_t)b * 3072 + h * 128 + dbase;
    float4 glv[3], grv[3];
    #pragma unroll
    for (int j = 0; j < 3; j++) glv[j] = ld4h(gl + base + j * 1024);
    #pragma unroll
    for (int i = 0; i < 3; i++) grv[i] = ld4h(gr + base + i * 1024);
    const float4 av = *reinterpret_cast<const float4*>(att + h * 128 + dbase);

    float e[3][3];
    #pragma unroll
    for (int i = 0; i < 3; i++)
        #pragma unroll
        for (int j = 0; j < 3; j++) {
            float s = av.x * lrelu02(glv[j].x + grv[i].x);
            s += av.y * lrelu02(glv[j].y + grv[i].y);
            s += av.z * lrelu02(glv[j].z + grv[i].z);
            s += av.w * lrelu02(glv[j].w + grv[i].w);
            e[i][j] = s;
        }
    #pragma unroll
    for (int i = 0; i < 3; i++)
        #pragma unroll
        for (int j = 0; j < 3; j++)
            #pragma unroll
            for (int o = 16; o > 0; o >>= 1)
                e[i][j] += __shfl_xor_sync(0xFFFFFFFFu, e[i][j], o);

    float alpha[3][3];
    #pragma unroll
    for (int i = 0; i < 3; i++) {
        float mx = fmaxf(e[i][0], fmaxf(e[i][1], e[i][2]));
        float p0 = __expf(e[i][0] - mx);
        float p1 = __expf(e[i][1] - mx);
        float p2 = __expf(e[i][2] - mx);
        float inv = 1.0f / (p0 + p1 + p2);
        alpha[i][0] = p0 * inv; alpha[i][1] = p1 * inv; alpha[i][2] = p2 * inv;
    }

    const float4 bb = *reinterpret_cast<const float4*>(b1 + h * 128 + dbase);
    #pragma unroll
    for (int i = 0; i < 3; i++) {
        float o[4];
        o[0] = alpha[i][0]*glv[0].x + alpha[i][1]*glv[1].x + alpha[i][2]*glv[2].x + bb.x;
        o[1] = alpha[i][0]*glv[0].y + alpha[i][1]*glv[1].y + alpha[i][2]*glv[2].y + bb.y;
        o[2] = alpha[i][0]*glv[0].z + alpha[i][1]*glv[1].z + alpha[i][2]*glv[2].z + bb.z;
        o[3] = alpha[i][0]*glv[0].w + alpha[i][1]*glv[1].w + alpha[i][2]*glv[2].w + bb.w;
        #pragma unroll
        for (int q = 0; q < 4; q++)
            o[q] = o[q] > 0.0f ? o[q] : (__expf(o[q]) - 1.0f);
        const size_t idx = (size_t)b * 3072 + i * 1024 + h * 128 + dbase;
        *reinterpret_cast<__half2*>(x1 + idx)     = __floats2half2_rn(o[0], o[1]);
        *reinterpret_cast<__half2*>(x1 + idx + 2) = __floats2half2_rn(o[2], o[3]);
    }
}

__global__ __launch_bounds__(256) void gat2_kernel(
    const fp16* __restrict__ gl, const fp16* __restrict__ gr,
    const float* __restrict__ att, const float* __restrict__ b2,
    float* __restrict__ out)
{
    const int b = blockIdx.x * 8 + (threadIdx.x >> 5);
    const int lane = threadIdx.x & 31;
    const fp16* glb = gl + (size_t)b * 3072;
    const fp16* grb = gr + (size_t)b * 3072;

    float e[9] = {0,0,0,0,0,0,0,0,0};
    #pragma unroll
    for (int c = 0; c < 8; c++) {
        const int d = c * 128 + lane * 4;
        const float4 av = *reinterpret_cast<const float4*>(att + d);
        float4 glv[3], grv[3];
        #pragma unroll
        for (int j = 0; j < 3; j++) glv[j] = ld4h(glb + j * 1024 + d);
        #pragma unroll
        for (int i = 0; i < 3; i++) grv[i] = ld4h(grb + i * 1024 + d);
        #pragma unroll
        for (int i = 0; i < 3; i++)
            #pragma unroll
            for (int j = 0; j < 3; j++) {
                float s = av.x * lrelu02(glv[j].x + grv[i].x);
                s += av.y * lrelu02(glv[j].y + grv[i].y);
                s += av.z * lrelu02(glv[j].z + grv[i].z);
                s += av.w * lrelu02(glv[j].w + grv[i].w);
                e[i * 3 + j] += s;
            }
    }
    #pragma unroll
    for (int k = 0; k < 9; k++)
        #pragma unroll
        for (int o = 16; o > 0; o >>= 1)
            e[k] += __shfl_xor_sync(0xFFFFFFFFu, e[k], o);

    float w[3] = {0.0f, 0.0f, 0.0f};
    #pragma unroll
    for (int i = 0; i < 3; i++) {
        float mx = fmaxf(e[i*3+0], fmaxf(e[i*3+1], e[i*3+2]));
        float p0 = __expf(e[i*3+0] - mx);
        float p1 = __expf(e[i*3+1] - mx);
        float p2 = __expf(e[i*3+2] - mx);
        float inv = 1.0f / (p0 + p1 + p2);
        w[0] += p0 * inv; w[1] += p1 * inv; w[2] += p2 * inv;
    }
    w[0] *= (1.0f/3.0f); w[1] *= (1.0f/3.0f); w[2] *= (1.0f/3.0f);

    #pragma unroll
    for (int c = 0; c < 8; c++) {
        const int d = c * 128 + lane * 4;
        const float4 bv = *reinterpret_cast<const float4*>(b2 + d);
        float4 g0 = ld4h(glb + 0 * 1024 + d);
        float4 g1 = ld4h(glb + 1 * 1024 + d);
        float4 g2 = ld4h(glb + 2 * 1024 + d);
        float4 o;
        o.x = w[0]*g0.x + w[1]*g1.x + w[2]*g2.x + bv.x;
        o.y = w[0]*g0.y + w[1]*g1.y + w[2]*g2.y + bv.y;
        o.z = w[0]*g0.z + w[1]*g1.z + w[2]*g2.z + bv.z;
        o.w = w[0]*g0.w + w[1]*g1.w + w[2]*g2.w + bv.w;
        *reinterpret_cast<float4*>(out + (size_t)b * 1024 + d) = o;
    }
}

// ---------------------------------------------------------------------------
// Launch
// ---------------------------------------------------------------------------
extern "C" void kernel_launch(void* const* d_in, const int* in_sizes, int n_in,
                              void* d_out, int out_size)
{
    const float* feats[3] = { (const float*)d_in[0], (const float*)d_in[1], (const float*)d_in[2] };
    const float* Wm[3]    = { (const float*)d_in[3], (const float*)d_in[5], (const float*)d_in[7] };
    const float* bt   = (const float*)d_in[4];
    const float* ba   = (const float*)d_in[6];
    const float* bv   = (const float*)d_in[8];
    const float* Wl1  = (const float*)d_in[9];
    const float* Wr1  = (const float*)d_in[10];
    const float* att1 = (const float*)d_in[11];
    const float* b1   = (const float*)d_in[12];
    const float* Wl2  = (const float*)d_in[13];
    const float* Wr2  = (const float*)d_in[14];
    const float* att2 = (const float*)d_in[15];
    const float* b2   = (const float*)d_in[16];
    float* out = (float*)d_out;

    float* bf;
    fp16 *gl1, *gr1, *gl2, *gr2;
    fp16 *WmH, *WT1H, *WT1L, *WT2, *WfT, *feat16, *x1;
    cudaGetSymbolAddress((void**)&bf,  g_bf);
    cudaGetSymbolAddress((void**)&gl1, g_gl1);
    cudaGetSymbolAddress((void**)&gr1, g_gr1);
    cudaGetSymbolAddress((void**)&gl2, g_gl2);
    cudaGetSymbolAddress((void**)&gr2, g_gr2);
    cudaGetSymbolAddress((void**)&WmH,  g_WmH);
    cudaGetSymbolAddress((void**)&WT1H, g_WT1H);
    cudaGetSymbolAddress((void**)&WT1L, g_WT1L);
    cudaGetSymbolAddress((void**)&WT2,  g_WT2);
    cudaGetSymbolAddress((void**)&WfT,  g_WfT);
    cudaGetSymbolAddress((void**)&feat16, g_feat);
    cudaGetSymbolAddress((void**)&x1, g_x1);

    cudaFuncSetAttribute(gemm_1t,
                         cudaFuncAttributeMaxDynamicSharedMemorySize, SMEM_1T);
    cudaFuncSetAttribute(gemm_fold,
                         cudaFuncAttributeMaxDynamicSharedMemorySize, SMEM_FOLD);

    const size_t M1 = 1024 * 1024;
    const float S_FOLD = 1024.0f;

    // 1. ALL prologue conversions + bias fold in one launch
    mega_prep<<<PREP_BLOCKS, 256>>>(
        Wl1, Wr1, Wl2, Wr2, Wm[0], Wm[1], Wm[2],
        feats[0], feats[1], feats[2], bt, ba, bv,
        WT1H, WT1L, WT2, WmH, feat16, bf, S_FOLD);

    // 2. fold GEMM -> WfT directly (transposed fp16 epilogue)
    gemm_fold<<<dim3(8, 8, 6), 256, SMEM_FOLD>>>(WmH, WT1H, WT1L, WfT,
                                                 1.0f / S_FOLD);

    // 3. layer-1 merged GEMMs, all 3 modalities, grid.z=3 (128-thread CTAs)
    gemm_1t<<<dim3(16, BATCH / 128, 3), 128, SMEM_1T>>>(
        BATCH, 1024,
        feat16, 1024, (size_t)BATCH * 1024,
        WfT, 1024, 2 * M1,
        gl1, gr1, 3072, 1024,
        bf, bf + 3 * 1024, 1024);

    // 4. GAT1 -> x1 (fp16)
    gat1_kernel<<<BATCH, 256>>>(gl1, gr1, att1, b1, x1);

    // 5. layer-2 merged GEMM
    gemm_1t<<<dim3(16, (3 * BATCH) / 128, 1), 128, SMEM_1T>>>(
        3 * BATCH, 1024,
        x1, 1024, 0,
        WT2, 1024, 0,
        gl2, gr2, 1024, 0,
        nullptr, nullptr, 0);

    // 6. GAT2 -> out
    gat2_kernel<<<BATCH / 8, 256>>>(gl2, gr2, att2, b2, out);
}

// round 16
// speedup vs baseline: 1.0032x; 1.0032x over previous
#include <cuda_runtime.h>
#include <cuda_fp16.h>
#include <cstdint>
#include <math.h>

// ---------------------------------------------------------------------------
// IntraSentenceGNN on GB300 (sm_103 base ISA): mma.sync fp16 GEMMs.
// R16: gat2 caches its gl loads (raw fp16 uint2) across both passes,
// eliminating the 201MB second-pass re-read. Rest identical to R15.
// ---------------------------------------------------------------------------

#define BATCH 32768
#define HDIM  1024

typedef __half fp16;

// ------------------------------ scratch -----------------------------------
__device__ __align__(256) float g_bf [6 * 1024];
__device__ __align__(256) fp16 g_gl1[BATCH * 3 * HDIM];
__device__ __align__(256) fp16 g_gr1[BATCH * 3 * HDIM];
__device__ __align__(256) fp16 g_gl2[BATCH * 3 * HDIM];
__device__ __align__(256) fp16 g_gr2[BATCH * 3 * HDIM];

__device__ __align__(256) fp16 g_WmH [3 * 1024 * 1024];
__device__ __align__(256) fp16 g_WT1H[2 * 1024 * 1024];
__device__ __align__(256) fp16 g_WT1L[2 * 1024 * 1024];
__device__ __align__(256) fp16 g_WT2 [2 * 1024 * 1024];   // [Wl2^T | Wr2^T]
__device__ __align__(256) fp16 g_WfT [6 * 1024 * 1024];   // c = 2m+side
__device__ __align__(256) fp16 g_feat[3 * BATCH * 1024];
__device__ __align__(256) fp16 g_x1  [BATCH * 3 * 1024];

// --------------------------- PTX helpers ----------------------------------
__device__ __forceinline__ uint32_t smem_u32(const void* p) {
    uint32_t a;
    asm("{ .reg .u64 t; cvta.to.shared.u64 t, %1; cvt.u32.u64 %0, t; }"
        : "=r"(a) : "l"(p));
    return a;
}
__device__ __forceinline__ void cp16(uint32_t sdst, const void* gsrc) {
    asm volatile("cp.async.cg.shared.global [%0], [%1], 16;" :: "r"(sdst), "l"(gsrc));
}
__device__ __forceinline__ void cp_commit() {
    asm volatile("cp.async.commit_group;" ::: "memory");
}
__device__ __forceinline__ void cp_wait1() {
    asm volatile("cp.async.wait_group 1;" ::: "memory");
}
__device__ __forceinline__ void cp_wait0() {
    asm volatile("cp.async.wait_group 0;" ::: "memory");
}

__device__ __forceinline__ uint32_t sw_addr(uint32_t base, int row, int colb) {
    uint32_t off = (uint32_t)(row * 128 + colb);
    return base + (off ^ ((off >> 3) & 0x70));
}

__device__ __forceinline__ void ldsm4(uint32_t addr, uint32_t* r) {
    asm volatile("ldmatrix.sync.aligned.m8n8.x4.shared.b16 {%0,%1,%2,%3}, [%4];"
        : "=r"(r[0]), "=r"(r[1]), "=r"(r[2]), "=r"(r[3]) : "r"(addr));
}

__device__ __forceinline__ void mma16816(float* c, const uint32_t* a, const uint32_t* b) {
    asm volatile(
        "mma.sync.aligned.m16n8k16.row.col.f32.f16.f16.f32 "
        "{%0,%1,%2,%3}, {%4,%5,%6,%7}, {%8,%9}, {%0,%1,%2,%3};"
        : "+f"(c[0]), "+f"(c[1]), "+f"(c[2]), "+f"(c[3])
        : "r"(a[0]), "r"(a[1]), "r"(a[2]), "r"(a[3]), "r"(b[0]), "r"(b[1]));
}

// load ROWS x 64 fp16 subtile (swizzled) via cp.async, NT threads
template<int ROWS, int NT>
__device__ __forceinline__ void load_sub(const fp16* src, int blk, int ld,
                                         uint32_t rb, int kofs, int tid) {
    #pragma unroll
    for (int i = 0; i < (ROWS * 8) / NT; i++) {
        const int c = tid + i * NT;
        const int row = c >> 3, kc = c & 7;
        const void* g = src + (size_t)(blk + row) * ld + kofs + kc * 8;
        uint32_t off = (uint32_t)(row * 128 + kc * 16);
        off ^= (off >> 3) & 0x70;
        cp16(rb + off, g);
    }
}

// ---------------------------------------------------------------------------
// 1-term fp16 GEMM (R14, unchanged): 128-thread CTA, warp 64x64 (2m x 2n),
// CTA 128x128, occ-2, BK=64, 3-stage cp.async, grid.z batching.
// ---------------------------------------------------------------------------
#define SMEM_1T (3 * 32768)

__global__ __launch_bounds__(128, 2) void gemm_1t(
    int M, int K,
    const fp16* __restrict__ A, int lda, size_t aZ,
    const fp16* __restrict__ B, int ldb, size_t bZ,
    fp16* __restrict__ Cl, fp16* __restrict__ Cr, int ldc, size_t cZ,
    const float* __restrict__ biasL, const float* __restrict__ biasR, int biasZ)
{
    const int z = blockIdx.z;
    A += (size_t)z * aZ;
    B += (size_t)z * bZ;
    Cl += (size_t)z * cZ;
    Cr += (size_t)z * cZ;
    if (biasL) { biasL += (size_t)z * biasZ; biasR += (size_t)z * biasZ; }

    extern __shared__ char smem[];
    const uint32_t sbase = smem_u32(smem);
    const int tid  = threadIdx.x;
    const int wid  = tid >> 5;
    const int lane = tid & 31;
    const int warp_m = wid & 1;
    const int warp_n = wid >> 1;

    const int mblk = blockIdx.y * 128;
    const int nblk = blockIdx.x * 128;
    const int side = nblk >> 10;
    fp16* C = side ? Cr : Cl;
    const float* bias = side ? biasR : biasL;
    const int colbase = nblk & 1023;
    const int KT = K >> 6;

    auto load_tile = [&](int kt, int s) {
        const uint32_t st = sbase + s * 32768;
        load_sub<128, 128>(A, mblk, lda, st,         kt * 64, tid);
        load_sub<128, 128>(B, nblk, ldb, st + 16384, kt * 64, tid);
        cp_commit();
    };

    float acc[4][8][4];
    #pragma unroll
    for (int mt = 0; mt < 4; mt++)
        #pragma unroll
        for (int nt = 0; nt < 8; nt++)
            #pragma unroll
            for (int q = 0; q < 4; q++) acc[mt][nt][q] = 0.0f;

    load_tile(0, 0);
    load_tile(1, 1);

    const int qa_r = ((lane >> 3) & 1) * 8 + (lane & 7);
    const int qa_c = (lane >> 4) * 16;
    const int qb_r = (lane >> 4) * 8 + (lane & 7);
    const int qb_c = ((lane >> 3) & 1) * 16;

    for (int kt = 0; kt < KT; kt++) {
        if (kt + 1 < KT) cp_wait1(); else cp_wait0();
        __syncthreads();

        const uint32_t st = sbase + (kt % 3) * 32768;
        const uint32_t sA = st, sB = st + 16384;

        #pragma unroll
        for (int ks = 0; ks < 4; ks++) {
            uint32_t afr[4][4];
            #pragma unroll
            for (int mt = 0; mt < 4; mt++)
                ldsm4(sw_addr(sA, warp_m * 64 + mt * 16 + qa_r, ks * 32 + qa_c), afr[mt]);
            uint32_t bfr[8][2];
            #pragma unroll
            for (int p = 0; p < 4; p++) {
                uint32_t r[4];
                ldsm4(sw_addr(sB, warp_n * 64 + p * 16 + qb_r, ks * 32 + qb_c), r);
                bfr[2*p][0] = r[0]; bfr[2*p][1] = r[1];
                bfr[2*p+1][0] = r[2]; bfr[2*p+1][1] = r[3];
            }
            #pragma unroll
            for (int mt = 0; mt < 4; mt++)
                #pragma unroll
                for (int nt = 0; nt < 8; nt++)
                    mma16816(acc[mt][nt], afr[mt], bfr[nt]);
        }
        if (kt + 2 < KT) load_tile(kt + 2, (kt + 2) % 3);
    }

    #pragma unroll
    for (int mt = 0; mt < 4; mt++) {
        const int row = mblk + warp_m * 64 + mt * 16 + (lane >> 2);
        #pragma unroll
        for (int nt = 0; nt < 8; nt++) {
            const int col = colbase + warp_n * 64 + nt * 8 + (lane & 3) * 2;
            float b0 = 0.0f, b1 = 0.0f;
            if (bias) { b0 = bias[col]; b1 = bias[col + 1]; }
            *reinterpret_cast<__half2*>(C + (size_t)row * ldc + col) =
                __floats2half2_rn(acc[mt][nt][0] + b0, acc[mt][nt][1] + b1);
            *reinterpret_cast<__half2*>(C + (size_t)(row + 8) * ldc + col) =
                __floats2half2_rn(acc[mt][nt][2] + b0, acc[mt][nt][3] + b1);
        }
    }
}

// ---------------------------------------------------------------------------
// 2-term fold GEMM with direct transposed fp16 output (R15, unchanged).
// ---------------------------------------------------------------------------
#define SMEM_FOLD (3 * 49152)

__global__ __launch_bounds__(256, 1) void gemm_fold(
    const fp16* __restrict__ WmH,
    const fp16* __restrict__ W1H, const fp16* __restrict__ W1L,
    fp16* __restrict__ WfT, float scale)
{
    const size_t M1 = 1024 * 1024;
    const int c = blockIdx.z;
    const int m = c >> 1, side = c & 1;
    const fp16* A  = WmH + (size_t)m * M1;
    const fp16* Bh = W1H + (size_t)side * M1;
    const fp16* Bl = W1L + (size_t)side * M1;
    fp16* Cout = WfT + (size_t)c * M1;

    extern __shared__ char smem[];
    const uint32_t sbase = smem_u32(smem);
    const int tid  = threadIdx.x;
    const int wid  = tid >> 5;
    const int lane = tid & 31;
    const int warp_m = wid & 3;
    const int warp_n = wid >> 2;

    const int mblk = blockIdx.y * 128;
    const int nblk = blockIdx.x * 128;
    const int KT = 16;

    auto load_tile = [&](int kt, int s) {
        const uint32_t st = sbase + s * 49152;
        load_sub<128, 256>(A,  mblk, 1024, st,         kt * 64, tid);
        load_sub<128, 256>(Bh, nblk, 1024, st + 16384, kt * 64, tid);
        load_sub<128, 256>(Bl, nblk, 1024, st + 32768, kt * 64, tid);
        cp_commit();
    };

    float acc[2][8][4];
    #pragma unroll
    for (int mt = 0; mt < 2; mt++)
        #pragma unroll
        for (int nt = 0; nt < 8; nt++)
            #pragma unroll
            for (int q = 0; q < 4; q++) acc[mt][nt][q] = 0.0f;

    load_tile(0, 0);
    load_tile(1, 1);

    const int qa_r = ((lane >> 3) & 1) * 8 + (lane & 7);
    const int qa_c = (lane >> 4) * 16;
    const int qb_r = (lane >> 4) * 8 + (lane & 7);
    const int qb_c = ((lane >> 3) & 1) * 16;

    for (int kt = 0; kt < KT; kt++) {
        if (kt + 1 < KT) cp_wait1(); else cp_wait0();
        __syncthreads();

        const uint32_t st = sbase + (kt % 3) * 49152;
        const uint32_t sA = st, sBh = st + 16384, sBl = st + 32768;

        #pragma unroll
        for (int ks = 0; ks < 4; ks++) {
            uint32_t afr[2][4];
            #pragma unroll
            for (int mt = 0; mt < 2; mt++)
                ldsm4(sw_addr(sA, warp_m * 32 + mt * 16 + qa_r, ks * 32 + qa_c), afr[mt]);
            uint32_t bfH[8][2], bfL[8][2];
            #pragma unroll
            for (int p = 0; p < 4; p++) {
                const int rr = warp_n * 64 + p * 16 + qb_r;
                const int cc = ks * 32 + qb_c;
                uint32_t r[4];
                ldsm4(sw_addr(sBh, rr, cc), r);
                bfH[2*p][0] = r[0]; bfH[2*p][1] = r[1];
                bfH[2*p+1][0] = r[2]; bfH[2*p+1][1] = r[3];
                ldsm4(sw_addr(sBl, rr, cc), r);
                bfL[2*p][0] = r[0]; bfL[2*p][1] = r[1];
                bfL[2*p+1][0] = r[2]; bfL[2*p+1][1] = r[3];
            }
            #pragma unroll
            for (int mt = 0; mt < 2; mt++)
                #pragma unroll
                for (int nt = 0; nt < 8; nt++) {
                    mma16816(acc[mt][nt], afr[mt], bfH[nt]);
                    mma16816(acc[mt][nt], afr[mt], bfL[nt]);
                }
        }
        if (kt + 2 < KT) load_tile(kt + 2, (kt + 2) % 3);
    }

    // ---- epilogue: stage fp16 tile in smem, write transposed ----
    __syncthreads();
    fp16* tile = reinterpret_cast<fp16*>(smem);   // [128][136] padded

    #pragma unroll
    for (int mt = 0; mt < 2; mt++) {
        const int row = warp_m * 32 + mt * 16 + (lane >> 2);
        #pragma unroll
        for (int nt = 0; nt < 8; nt++) {
            const int col = warp_n * 64 + nt * 8 + (lane & 3) * 2;
            *reinterpret_cast<__half2*>(tile + row * 136 + col) =
                __floats2half2_rn(acc[mt][nt][0] * scale, acc[mt][nt][1] * scale);
            *reinterpret_cast<__half2*>(tile + (row + 8) * 136 + col) =
                __floats2half2_rn(acc[mt][nt][2] * scale, acc[mt][nt][3] * scale);
        }
    }
    __syncthreads();

    #pragma unroll
    for (int i = 0; i < 32; i++) {
        const int idx = tid + i * 256;
        const int tr = (idx & 63) * 2;
        const int tc = idx >> 6;
        __half2 v = __halves2half2(tile[tr * 136 + tc], tile[(tr + 1) * 136 + tc]);
        *reinterpret_cast<__half2*>(Cout + (size_t)(nblk + tc) * 1024 + mblk + tr) = v;
    }
}

// ---------------------------------------------------------------------------
// mega_prep (unchanged)
// ---------------------------------------------------------------------------
__device__ __forceinline__ void split1(float x, fp16& h, fp16& l) {
    h = __float2half(x);
    l = __float2half(x - __half2float(h));
}

#define PREP_BLOCKS 19480

__global__ __launch_bounds__(256) void mega_prep(
    const float* __restrict__ Wl1, const float* __restrict__ Wr1,
    const float* __restrict__ Wl2, const float* __restrict__ Wr2,
    const float* __restrict__ Wm0, const float* __restrict__ Wm1,
    const float* __restrict__ Wm2,
    const float* __restrict__ f0, const float* __restrict__ f1,
    const float* __restrict__ f2,
    const float* __restrict__ bt, const float* __restrict__ ba,
    const float* __restrict__ bv,
    fp16* __restrict__ WT1H, fp16* __restrict__ WT1L, fp16* __restrict__ WT2,
    fp16* __restrict__ WmH, fp16* __restrict__ feat16,
    float* __restrict__ bf, float sfold)
{
    const size_t M1 = 1024 * 1024;
    __shared__ float t[32][33];
    const int bid = blockIdx.x;
    const int tid = threadIdx.x;
    const int tx = tid & 31, ty = tid >> 5;

    if (bid < 2048) {
        const int z = bid >> 10, tl = bid & 1023;
        const float* in = z ? Wr1 : Wl1;
        fp16* hi = WT1H + (size_t)z * M1;
        fp16* lo = WT1L + (size_t)z * M1;
        const int x0 = (tl & 31) * 32, y0 = (tl >> 5) * 32;
        #pragma unroll
        for (int r = ty; r < 32; r += 8)
            t[r][tx] = in[(size_t)(y0 + r) * 1024 + x0 + tx];
        __syncthreads();
        #pragma unroll
        for (int r = ty; r < 32; r += 8) {
            float v = t[tx][r] * sfold;
            fp16 h, l;
            split1(v, h, l);
            hi[(size_t)(x0 + r) * 1024 + y0 + tx] = h;
            lo[(size_t)(x0 + r) * 1024 + y0 + tx] = l;
        }
    } else if (bid < 4096) {
        const int rel = bid - 2048;
        const int z = rel >> 10, tl = rel & 1023;
        const float* in = z ? Wr2 : Wl2;
        fp16* o = WT2 + (size_t)z * M1;
        const int x0 = (tl & 31) * 32, y0 = (tl >> 5) * 32;
        #pragma unroll
        for (int r = ty; r < 32; r += 8)
            t[r][tx] = in[(size_t)(y0 + r) * 1024 + x0 + tx];
        __syncthreads();
        #pragma unroll
        for (int r = ty; r < 32; r += 8)
            o[(size_t)(x0 + r) * 1024 + y0 + tx] = __float2half(t[tx][r]);
    } else if (bid < 7168) {
        const int rel = bid - 4096;
        const int m = rel >> 10, blk = rel & 1023;
        const float* in = (m == 0) ? Wm0 : (m == 1) ? Wm1 : Wm2;
        fp16* o = WmH + (size_t)m * M1;
        const int i = blk * 1024 + tid * 4;
        float4 v = *reinterpret_cast<const float4*>(in + i);
        *reinterpret_cast<__half2*>(o + i)     = __floats2half2_rn(v.x, v.y);
        *reinterpret_cast<__half2*>(o + i + 2) = __floats2half2_rn(v.z, v.w);
    } else if (bid < 19456) {
        const int rel = bid - 7168;
        const int m = rel / 4096, blk = rel % 4096;
        const float* in = (m == 0) ? f0 : (m == 1) ? f1 : f2;
        fp16* o = feat16 + (size_t)m * BATCH * 1024;
        const int base = blk * 8192;
        #pragma unroll
        for (int u = 0; u < 8; u++) {
            const int i = base + (u * 256 + tid) * 4;
            float4 v = *reinterpret_cast<const float4*>(in + i);
            *reinterpret_cast<__half2*>(o + i)     = __floats2half2_rn(v.x, v.y);
            *reinterpret_cast<__half2*>(o + i + 2) = __floats2half2_rn(v.z, v.w);
        }
    } else {
        const int g = (bid - 19456) * 256 + tid;
        const int combo = g >> 10, j = g & 1023;
        const int m = combo % 3;
        const float* bvec = (m == 0) ? bt : (m == 1) ? ba : bv;
        const float* W = (combo < 3) ? Wl1 : Wr1;
        float s = 0.0f;
        for (int k = 0; k < 1024; k++) s += bvec[k] * W[k * 1024 + j];
        bf[g] = s;
    }
}

// ---------------------------------------------------------------------------
// attention kernels
// ---------------------------------------------------------------------------
__device__ __forceinline__ float lrelu02(float x) { return x > 0.0f ? x : 0.2f * x; }

__device__ __forceinline__ float4 ld4h(const fp16* p) {
    uint2 u = *reinterpret_cast<const uint2*>(p);
    float2 f01 = __half22float2(*reinterpret_cast<__half2*>(&u.x));
    float2 f23 = __half22float2(*reinterpret_cast<__half2*>(&u.y));
    return make_float4(f01.x, f01.y, f23.x, f23.y);
}
__device__ __forceinline__ float4 cvt4h(uint2 u) {
    float2 f01 = __half22float2(*reinterpret_cast<__half2*>(&u.x));
    float2 f23 = __half22float2(*reinterpret_cast<__half2*>(&u.y));
    return make_float4(f01.x, f01.y, f23.x, f23.y);
}

__global__ __launch_bounds__(256) void gat1_kernel(
    const fp16* __restrict__ gl, const fp16* __restrict__ gr,
    const float* __restrict__ att, const float* __restrict__ b1,
    fp16* __restrict__ x1)
{
    const int b = blockIdx.x;
    const int h = threadIdx.x >> 5;
    const int lane = threadIdx.x & 31;
    const int dbase = lane * 4;

    const size_t base = (size_t)b * 3072 + h * 128 + dbase;
    float4 glv[3], grv[3];
    #pragma unroll
    for (int j = 0; j < 3; j++) glv[j] = ld4h(gl + base + j * 1024);
    #pragma unroll
    for (int i = 0; i < 3; i++) grv[i] = ld4h(gr + base + i * 1024);
    const float4 av = *reinterpret_cast<const float4*>(att + h * 128 + dbase);

    float e[3][3];
    #pragma unroll
    for (int i = 0; i < 3; i++)
        #pragma unroll
        for (int j = 0; j < 3; j++) {
            float s = av.x * lrelu02(glv[j].x + grv[i].x);
            s += av.y * lrelu02(glv[j].y + grv[i].y);
            s += av.z * lrelu02(glv[j].z + grv[i].z);
            s += av.w * lrelu02(glv[j].w + grv[i].w);
            e[i][j] = s;
        }
    #pragma unroll
    for (int i = 0; i < 3; i++)
        #pragma unroll
        for (int j = 0; j < 3; j++)
            #pragma unroll
            for (int o = 16; o > 0; o >>= 1)
                e[i][j] += __shfl_xor_sync(0xFFFFFFFFu, e[i][j], o);

    float alpha[3][3];
    #pragma unroll
    for (int i = 0; i < 3; i++) {
        float mx = fmaxf(e[i][0], fmaxf(e[i][1], e[i][2]));
        float p0 = __expf(e[i][0] - mx);
        float p1 = __expf(e[i][1] - mx);
        float p2 = __expf(e[i][2] - mx);
        float inv = 1.0f / (p0 + p1 + p2);
        alpha[i][0] = p0 * inv; alpha[i][1] = p1 * inv; alpha[i][2] = p2 * inv;
    }

    const float4 bb = *reinterpret_cast<const float4*>(b1 + h * 128 + dbase);
    #pragma unroll
    for (int i = 0; i < 3; i++) {
        float o[4];
        o[0] = alpha[i][0]*glv[0].x + alpha[i][1]*glv[1].x + alpha[i][2]*glv[2].x + bb.x;
        o[1] = alpha[i][0]*glv[0].y + alpha[i][1]*glv[1].y + alpha[i][2]*glv[2].y + bb.y;
        o[2] = alpha[i][0]*glv[0].z + alpha[i][1]*glv[1].z + alpha[i][2]*glv[2].z + bb.z;
        o[3] = alpha[i][0]*glv[0].w + alpha[i][1]*glv[1].w + alpha[i][2]*glv[2].w + bb.w;
        #pragma unroll
        for (int q = 0; q < 4; q++)
            o[q] = o[q] > 0.0f ? o[q] : (__expf(o[q]) - 1.0f);
        const size_t idx = (size_t)b * 3072 + i * 1024 + h * 128 + dbase;
        *reinterpret_cast<__half2*>(x1 + idx)     = __floats2half2_rn(o[0], o[1]);
        *reinterpret_cast<__half2*>(x1 + idx + 2) = __floats2half2_rn(o[2], o[3]);
    }
}

// R16: gl loads cached as raw fp16 across both passes (no second DRAM read)
__global__ __launch_bounds__(256) void gat2_kernel(
    const fp16* __restrict__ gl, const fp16* __restrict__ gr,
    const float* __restrict__ att, const float* __restrict__ b2,
    float* __restrict__ out)
{
    const int b = blockIdx.x * 8 + (threadIdx.x >> 5);
    const int lane = threadIdx.x & 31;
    const fp16* glb = gl + (size_t)b * 3072;
    const fp16* grb = gr + (size_t)b * 3072;

    uint2 glraw[8][3];     // cached raw fp16 (48 regs)

    float e[9] = {0,0,0,0,0,0,0,0,0};
    #pragma unroll
    for (int c = 0; c < 8; c++) {
        const int d = c * 128 + lane * 4;
        const float4 av = *reinterpret_cast<const float4*>(att + d);
        float4 glv[3], grv[3];
        #pragma unroll
        for (int j = 0; j < 3; j++) {
            glraw[c][j] = *reinterpret_cast<const uint2*>(glb + j * 1024 + d);
            glv[j] = cvt4h(glraw[c][j]);
        }
        #pragma unroll
        for (int i = 0; i < 3; i++) grv[i] = ld4h(grb + i * 1024 + d);
        #pragma unroll
        for (int i = 0; i < 3; i++)
            #pragma unroll
            for (int j = 0; j < 3; j++) {
                float s = av.x * lrelu02(glv[j].x + grv[i].x);
                s += av.y * lrelu02(glv[j].y + grv[i].y);
                s += av.z * lrelu02(glv[j].z + grv[i].z);
                s += av.w * lrelu02(glv[j].w + grv[i].w);
                e[i * 3 + j] += s;
            }
    }
    #pragma unroll
    for (int k = 0; k < 9; k++)
        #pragma unroll
        for (int o = 16; o > 0; o >>= 1)
            e[k] += __shfl_xor_sync(0xFFFFFFFFu, e[k], o);

    float w[3] = {0.0f, 0.0f, 0.0f};
    #pragma unroll
    for (int i = 0; i < 3; i++) {
        float mx = fmaxf(e[i*3+0], fmaxf(e[i*3+1], e[i*3+2]));
        float p0 = __expf(e[i*3+0] - mx);
        float p1 = __expf(e[i*3+1] - mx);
        float p2 = __expf(e[i*3+2] - mx);
        float inv = 1.0f / (p0 + p1 + p2);
        w[0] += p0 * inv; w[1] += p1 * inv; w[2] += p2 * inv;
    }
    w[0] *= (1.0f/3.0f); w[1] *= (1.0f/3.0f); w[2] *= (1.0f/3.0f);

    #pragma unroll
    for (int c = 0; c < 8; c++) {
        const int d = c * 128 + lane * 4;
        const float4 bv = *reinterpret_cast<const float4*>(b2 + d);
        float4 g0 = cvt4h(glraw[c][0]);
        float4 g1 = cvt4h(glraw[c][1]);
        float4 g2 = cvt4h(glraw[c][2]);
        float4 o;
        o.x = w[0]*g0.x + w[1]*g1.x + w[2]*g2.x + bv.x;
        o.y = w[0]*g0.y + w[1]*g1.y + w[2]*g2.y + bv.y;
        o.z = w[0]*g0.z + w[1]*g1.z + w[2]*g2.z + bv.z;
        o.w = w[0]*g0.w + w[1]*g1.w + w[2]*g2.w + bv.w;
        *reinterpret_cast<float4*>(out + (size_t)b * 1024 + d) = o;
    }
}

// ---------------------------------------------------------------------------
// Launch
// ---------------------------------------------------------------------------
extern "C" void kernel_launch(void* const* d_in, const int* in_sizes, int n_in,
                              void* d_out, int out_size)
{
    const float* feats[3] = { (const float*)d_in[0], (const float*)d_in[1], (const float*)d_in[2] };
    const float* Wm[3]    = { (const float*)d_in[3], (const float*)d_in[5], (const float*)d_in[7] };
    const float* bt   = (const float*)d_in[4];
    const float* ba   = (const float*)d_in[6];
    const float* bv   = (const float*)d_in[8];
    const float* Wl1  = (const float*)d_in[9];
    const float* Wr1  = (const float*)d_in[10];
    const float* att1 = (const float*)d_in[11];
    const float* b1   = (const float*)d_in[12];
    const float* Wl2  = (const float*)d_in[13];
    const float* Wr2  = (const float*)d_in[14];
    const float* att2 = (const float*)d_in[15];
    const float* b2   = (const float*)d_in[16];
    float* out = (float*)d_out;

    float* bf;
    fp16 *gl1, *gr1, *gl2, *gr2;
    fp16 *WmH, *WT1H, *WT1L, *WT2, *WfT, *feat16, *x1;
    cudaGetSymbolAddress((void**)&bf,  g_bf);
    cudaGetSymbolAddress((void**)&gl1, g_gl1);
    cudaGetSymbolAddress((void**)&gr1, g_gr1);
    cudaGetSymbolAddress((void**)&gl2, g_gl2);
    cudaGetSymbolAddress((void**)&gr2, g_gr2);
    cudaGetSymbolAddress((void**)&WmH,  g_WmH);
    cudaGetSymbolAddress((void**)&WT1H, g_WT1H);
    cudaGetSymbolAddress((void**)&WT1L, g_WT1L);
    cudaGetSymbolAddress((void**)&WT2,  g_WT2);
    cudaGetSymbolAddress((void**)&WfT,  g_WfT);
    cudaGetSymbolAddress((void**)&feat16, g_feat);
    cudaGetSymbolAddress((void**)&x1, g_x1);

    cudaFuncSetAttribute(gemm_1t,
                         cudaFuncAttributeMaxDynamicSharedMemorySize, SMEM_1T);
    cudaFuncSetAttribute(gemm_fold,
                         cudaFuncAttributeMaxDynamicSharedMemorySize, SMEM_FOLD);

    const size_t M1 = 1024 * 1024;
    const float S_FOLD = 1024.0f;

    // 1. ALL prologue conversions + bias fold in one launch
    mega_prep<<<PREP_BLOCKS, 256>>>(
        Wl1, Wr1, Wl2, Wr2, Wm[0], Wm[1], Wm[2],
        feats[0], feats[1], feats[2], bt, ba, bv,
        WT1H, WT1L, WT2, WmH, feat16, bf, S_FOLD);

    // 2. fold GEMM -> WfT directly (transposed fp16 epilogue)
    gemm_fold<<<dim3(8, 8, 6), 256, SMEM_FOLD>>>(WmH, WT1H, WT1L, WfT,
                                                 1.0f / S_FOLD);

    // 3. layer-1 merged GEMMs, all 3 modalities, grid.z=3 (128-thread CTAs)
    gemm_1t<<<dim3(16, BATCH / 128, 3), 128, SMEM_1T>>>(
        BATCH, 1024,
        feat16, 1024, (size_t)BATCH * 1024,
        WfT, 1024, 2 * M1,
        gl1, gr1, 3072, 1024,
        bf, bf + 3 * 1024, 1024);

    // 4. GAT1 -> x1 (fp16)
    gat1_kernel<<<BATCH, 256>>>(gl1, gr1, att1, b1, x1);

    // 5. layer-2 merged GEMM
    gemm_1t<<<dim3(16, (3 * BATCH) / 128, 1), 128, SMEM_1T>>>(
        3 * BATCH, 1024,
        x1, 1024, 0,
        WT2, 1024, 0,
        gl2, gr2, 1024, 0,
        nullptr, nullptr, 0);

    // 6. GAT2 -> out
    gat2_kernel<<<BATCH / 8, 256>>>(gl2, gr2, att2, b2, out);
}